// round 6
// baseline (speedup 1.0000x reference)
#include <cuda_runtime.h>
#include <cstdint>

// OccupancyPooling: N=8192, 6x6 relative occupancy over all 67M pairs, then
// Linear(36 -> 128).
//
// R6 vs R5 (45.5us = ~27.5 count + 18.0 fused gemm):
//  - UNDO the reduce+gemm fusion (90 regs / occ 20% / serial strided LDG chain).
//  - standalone reduce: 73728 threads, 64 coalesced uint LDGs each (g_part is
//    18.9MB -> fully L2-resident right after the count kernel), unsigned dp4a
//    byte sums, float4 stores. Bandwidth-bound at L2 speed.
//  - gemm: lean R3 shape (ROWS2=16, 8 acc/thread, 512 blocks, high occupancy).
//  - count kernel unchanged (issue-bound at ~13 inst/pair, 48 warps/SM).

#define N_AGENTS 8192
#define NCELL    36
#define HIDDEN   128
#define T1       128
#define CHUNK    128                    // 64 chunks * 128 = 8192 exact
#define S_CHUNKS 64
#define I_TILES  (N_AGENTS / T1)        // 64 -> grid 64x64 = 4096 blocks

#define TRD      256                    // reduce threads/block
#define T2       256
#define ROWS2    16                     // 512 gemm blocks

// Partial histograms [chunk][cell][agent] u8 (max count per chunk <= 128).
// Fully rewritten every launch -> deterministic, no zeroing.
__device__ unsigned char g_part[S_CHUNKS][NCELL][N_AGENTS];
// Reduced occupancy, cell-major (coalesced in both reduce and gemm).
__device__ float g_occ[NCELL][N_AGENTS];

__device__ __forceinline__ unsigned long long pack2(float lo, float hi) {
    unsigned long long r;
    asm("mov.b64 %0, {%1, %2};" : "=l"(r) : "f"(lo), "f"(hi));
    return r;
}

// One pair, bit-exact vs reference:
//   d = rn(pj - pi)       packed FADD2 (negation exact)
//   r = rn(d*2 + 3)       packed FFMA2 (d*2 exact -> single rounding == ref)
//   m = rd(r + 2^23)      packed FADD2.RM magic floor: bits = 0x4B000000 +
//                         floor(r) for r in [0,2^23); bits < 0x4B000000 if r<0
__device__ __forceinline__ void count_pair(unsigned long long xy,
                                           unsigned long long negxy,
                                           unsigned long long two2,
                                           unsigned long long three2,
                                           unsigned long long magic2,
                                           char* __restrict__ cnt_t) {
    unsigned long long d, r, m;
    asm("add.rn.f32x2 %0, %1, %2;" : "=l"(d) : "l"(xy), "l"(negxy));
    asm("fma.rn.f32x2 %0, %1, %2, %3;" : "=l"(r) : "l"(d), "l"(two2), "l"(three2));
    asm("add.rm.f32x2 %0, %1, %2;" : "=l"(m) : "l"(r), "l"(magic2));
    unsigned bu, bv;
    asm("mov.b64 {%0, %1}, %2;" : "=r"(bu), "=r"(bv) : "l"(m));
    // byte offset: (bu*6+bv)*512 wraps (mod 2^32) to slot*512 exactly
    // (7*0x4B000000*512 == 26*2^32). Only dereferenced when in range.
    const unsigned offb = (bu * 6u + bv) * 512u;
    if ((bu - 0x4B000000u) < 6u && (bv - 0x4B000000u) < 6u)
        *(unsigned*)(cnt_t + offb) += 1u;   // [slot][tid]: bank=tid%32, no conflicts
}

__global__ __launch_bounds__(T1, 12) void occ_count_kernel(const float2* __restrict__ obs) {
    __shared__ __align__(16) float2 sobs[CHUNK];   // 1024 B
    __shared__ unsigned cnt[NCELL * T1];           // [slot][tid], 18432 B

    const int tid = threadIdx.x;
    const int i   = blockIdx.x * T1 + tid;
    const int s   = blockIdx.y;

    sobs[tid] = obs[s * CHUNK + tid];

    #pragma unroll
    for (int c = 0; c < NCELL; c++) cnt[c * T1 + tid] = 0u;

    const float2 pi = obs[i];
    const unsigned long long negxy  = pack2(-pi.x, -pi.y);
    const unsigned long long two2   = pack2(2.0f, 2.0f);
    const unsigned long long three2 = pack2(3.0f, 3.0f);
    const unsigned long long magic2 = pack2(8388608.0f, 8388608.0f);
    char* cnt_t = (char*)(cnt + tid);

    __syncthreads();

    const float4* s4 = (const float4*)sobs;        // 2 pairs per LDS.128
    #pragma unroll 8
    for (int jj = 0; jj < CHUNK / 2; jj++) {
        const float4 p = s4[jj];
        unsigned long long xy0, xy1;
        asm("mov.b64 %0, {%1, %2};" : "=l"(xy0) : "f"(p.x), "f"(p.y));
        asm("mov.b64 %0, {%1, %2};" : "=l"(xy1) : "f"(p.z), "f"(p.w));
        count_pair(xy0, negxy, two2, three2, magic2, cnt_t);
        count_pair(xy1, negxy, two2, three2, magic2, cnt_t);
    }

    #pragma unroll
    for (int c = 0; c < NCELL; c++)
        g_part[s][c][i] = (unsigned char)cnt[c * T1 + tid];   // coalesced u8
}

// Reduce 64 u8 partials -> f32. One thread per (cell, 4-agent quad):
// 64 coalesced uint LDGs (L2-resident), unsigned dp4a byte sums (counts can
// reach 128, so UNSIGNED is required), subtract the self pair (always cell 21:
// rel=(3,3) for j==i, no NaNs), float4 store.
__global__ __launch_bounds__(TRD) void occ_reduce_kernel() {
    const int gid = blockIdx.x * TRD + threadIdx.x;  // 0..73727
    const int c = gid >> 11;                         // / (8192/4) quads per cell
    const int i = (gid & 2047) * 4;
    unsigned a0 = 0, a1 = 0, a2 = 0, a3 = 0;
    #pragma unroll
    for (int s = 0; s < S_CHUNKS; s++) {
        const unsigned w = *(const unsigned*)&g_part[s][c][i];
        a0 = __dp4a(w, 0x00000001u, a0);
        a1 = __dp4a(w, 0x00000100u, a1);
        a2 = __dp4a(w, 0x00010000u, a2);
        a3 = __dp4a(w, 0x01000000u, a3);
    }
    const float self = (c == 21) ? 1.0f : 0.0f;
    float4 f;
    f.x = (float)a0 - self;
    f.y = (float)a1 - self;
    f.z = (float)a2 - self;
    f.w = (float)a3 - self;
    *(float4*)&g_occ[c][i] = f;
}

__global__ __launch_bounds__(T2) void occ_gemm_kernel(
    const float* __restrict__ W,   // [128, 36] row-major
    const float* __restrict__ b,   // [128]
    float* __restrict__ out)       // [8192, 128]
{
    __shared__ float Ws[HIDDEN * 37];          // stride-37 pad: conflict-free
    __shared__ float occs[ROWS2 * NCELL];

    const int tid   = threadIdx.x;
    const int rbase = blockIdx.x * ROWS2;

    for (int idx = tid; idx < HIDDEN * NCELL; idx += T2) {
        const int h = idx / NCELL, c = idx - h * NCELL;
        Ws[h * 37 + c] = W[idx];
    }
    for (int idx = tid; idx < ROWS2 * NCELL; idx += T2) {
        const int c = idx >> 4;                // 16 consecutive rows per c
        const int r = idx & (ROWS2 - 1);
        occs[r * NCELL + c] = g_occ[c][rbase + r];
    }
    __syncthreads();

    const int h  = tid & (HIDDEN - 1);         // lanes -> consecutive h
    const int hy = tid >> 7;                   // row half (uniform per warp)
    const float bh = b[h];

    float acc[8];
    #pragma unroll
    for (int k = 0; k < 8; k++) acc[k] = bh;

    #pragma unroll
    for (int c = 0; c < NCELL; c++) {
        const float wc = Ws[h * 37 + c];       // conflict-free
        const float* oc = &occs[(hy * 8) * NCELL + c];
        #pragma unroll
        for (int k = 0; k < 8; k++)
            acc[k] = fmaf(oc[k * NCELL], wc, acc[k]);   // warp-broadcast
    }

    #pragma unroll
    for (int k = 0; k < 8; k++)
        out[(rbase + hy * 8 + k) * HIDDEN + h] = acc[k];    // coalesced
}

extern "C" void kernel_launch(void* const* d_in, const int* in_sizes, int n_in,
                              void* d_out, int out_size) {
    const float2* obs = (const float2*)d_in[0];   // [8192, 2] f32
    const float*  W   = (const float*) d_in[1];   // [128, 36] f32
    const float*  b   = (const float*) d_in[2];   // [128] f32
    float* out = (float*)d_out;                   // [8192, 128] f32

    dim3 g1(I_TILES, S_CHUNKS);                   // 64 x 64 = 4096 blocks
    occ_count_kernel<<<g1, T1>>>(obs);
    occ_reduce_kernel<<<(NCELL * N_AGENTS / 4) / TRD, TRD>>>();   // 288 blocks
    occ_gemm_kernel<<<N_AGENTS / ROWS2, T2>>>(W, b, out);
}